// round 2
// baseline (speedup 1.0000x reference)
#include <cuda_runtime.h>
#include <cstdint>

#define NB     2048
#define NCELLS 96
#define NLINES 24
#define ND     512
#define NROWS  (NB * NLINES)   // 49152

// -------- scratch (device globals; allocation-free) --------
__device__ __align__(16) float g_LC[(size_t)NROWS * ND];
__device__ __align__(16) float g_GC[(size_t)NB * ND];
__device__ __align__(16) float g_H [(size_t)NROWS * ND];
__device__ __align__(16) float g_P [(size_t)NROWS * ND];
__device__ __align__(16) float g_Hg[(size_t)NB * ND];
__device__ __align__(16) float g_S [(size_t)NB * ND];

// ============================================================
// Kernel 1: per-batch reduction.  LC[b,l,:] = mean of 4 cells,
// GC[b,:] = mean of 96 cells.  One CTA per b, 128 threads, float4.
// ============================================================
__global__ void reduce_kernel(const float* __restrict__ x)
{
    const int b = blockIdx.x;
    const int t = threadIdx.x;                       // 0..127, owns 4 d's
    const float4* xr = reinterpret_cast<const float4*>(x) + (size_t)b * NCELLS * (ND/4) + t;
    float4* lc = reinterpret_cast<float4*>(g_LC) + (size_t)b * NLINES * (ND/4) + t;

    float tx = 0.f, ty = 0.f, tz = 0.f, tw = 0.f;
    #pragma unroll 4
    for (int g = 0; g < NLINES; g++) {
        float4 v0 = xr[(g*4 + 0) * (ND/4)];
        float4 v1 = xr[(g*4 + 1) * (ND/4)];
        float4 v2 = xr[(g*4 + 2) * (ND/4)];
        float4 v3 = xr[(g*4 + 3) * (ND/4)];
        float sx = v0.x + v1.x + v2.x + v3.x;
        float sy = v0.y + v1.y + v2.y + v3.y;
        float sz = v0.z + v1.z + v2.z + v3.z;
        float sw = v0.w + v1.w + v2.w + v3.w;
        lc[g * (ND/4)] = make_float4(sx * 0.25f, sy * 0.25f, sz * 0.25f, sw * 0.25f);
        tx += sx; ty += sy; tz += sz; tw += sw;
    }
    const float inv96 = 1.0f / 96.0f;
    reinterpret_cast<float4*>(g_GC)[(size_t)b * (ND/4) + t] =
        make_float4(tx * inv96, ty * inv96, tz * inv96, tw * inv96);
}

// ============================================================
// TF32 GEMM: C[M,512] = act(A[M,512] @ W[512,512] + bias)
// BM=128 BN=64 BK=16, 256 threads (8 warps, 4m x 2n, warp tile 32x32)
// mma.sync.aligned.m16n8k8.row.col.f32.tf32.tf32.f32
// ============================================================
__device__ __forceinline__ uint32_t f2tf32(float f)
{
    uint32_t u;
    asm("cvt.rna.tf32.f32 %0, %1;" : "=r"(u) : "f"(f));
    return u;
}

__device__ __forceinline__ float mish_f(float v)
{
    float sp = log1pf(expf(v));   // expf overflow -> inf -> tanh(inf)=1 -> v (correct limit)
    return v * tanhf(sp);
}

template<bool MISH>
__global__ void __launch_bounds__(256)
gemm_kernel(const float* __restrict__ A, const float* __restrict__ W,
            const float* __restrict__ bias, float* __restrict__ C)
{
    // padding strides chosen so fragment reads are bank-conflict free
    __shared__ float As[2][128][20];   // BK=16, pad to 20
    __shared__ float Bs[2][16][72];    // BN=64, pad to 72

    const int tid  = threadIdx.x;
    const int lane = tid & 31;
    const int warp = tid >> 5;
    const int wm = (warp >> 1) * 32;   // warp M offset within 128
    const int wn = (warp & 1) * 32;    // warp N offset within 64

    const size_t bm = (size_t)blockIdx.x * 128;
    const int    bn = blockIdx.y * 64;

    // global load mapping
    const int arow = tid >> 1;             // 0..127
    const int acol = (tid & 1) * 8;        // 0 or 8
    const int brow = tid >> 4;             // 0..15
    const int bcol = (tid & 15) * 4;       // 0..60

    const float* gA = A + (bm + arow) * (size_t)ND + acol;
    const float* gB = W + (size_t)brow * ND + bn + bcol;

    const uint32_t aAddr0 = (uint32_t)__cvta_generic_to_shared(&As[0][arow][acol]);
    const uint32_t bAddr0 = (uint32_t)__cvta_generic_to_shared(&Bs[0][brow][bcol]);
    const uint32_t aBufStride = 128 * 20 * 4;
    const uint32_t bBufStride = 16 * 72 * 4;

    float acc[2][4][4];
    #pragma unroll
    for (int i = 0; i < 2; i++)
        #pragma unroll
        for (int j = 0; j < 4; j++)
            #pragma unroll
            for (int k = 0; k < 4; k++) acc[i][j][k] = 0.f;

    auto issue = [&](int ki, int buf) {
        const float* pa = gA + ki * 16;
        uint32_t da = aAddr0 + buf * aBufStride;
        asm volatile("cp.async.cg.shared.global [%0], [%1], 16;\n" :: "r"(da),      "l"(pa));
        asm volatile("cp.async.cg.shared.global [%0], [%1], 16;\n" :: "r"(da + 16), "l"(pa + 4));
        const float* pb = gB + (size_t)ki * 16 * ND;
        uint32_t db = bAddr0 + buf * bBufStride;
        asm volatile("cp.async.cg.shared.global [%0], [%1], 16;\n" :: "r"(db), "l"(pb));
        asm volatile("cp.async.commit_group;\n");
    };

    issue(0, 0);

    for (int i = 0; i < 32; i++) {
        asm volatile("cp.async.wait_group 0;\n");
        __syncthreads();                       // tile ready + all threads done with prior compute
        if (i < 31) issue(i + 1, (i + 1) & 1);
        const int buf = i & 1;

        #pragma unroll
        for (int ks = 0; ks < 16; ks += 8) {
            uint32_t af[2][4], bf[4][2];
            #pragma unroll
            for (int mt = 0; mt < 2; mt++) {
                int r = wm + mt * 16 + (lane >> 2);
                int c = ks + (lane & 3);
                af[mt][0] = f2tf32(As[buf][r    ][c    ]);
                af[mt][1] = f2tf32(As[buf][r + 8][c    ]);
                af[mt][2] = f2tf32(As[buf][r    ][c + 4]);
                af[mt][3] = f2tf32(As[buf][r + 8][c + 4]);
            }
            #pragma unroll
            for (int nt = 0; nt < 4; nt++) {
                int cc = wn + nt * 8 + (lane >> 2);
                bf[nt][0] = f2tf32(Bs[buf][ks + (lane & 3)    ][cc]);
                bf[nt][1] = f2tf32(Bs[buf][ks + (lane & 3) + 4][cc]);
            }
            #pragma unroll
            for (int mt = 0; mt < 2; mt++)
                #pragma unroll
                for (int nt = 0; nt < 4; nt++) {
                    asm volatile(
                        "mma.sync.aligned.m16n8k8.row.col.f32.tf32.tf32.f32 "
                        "{%0,%1,%2,%3},{%4,%5,%6,%7},{%8,%9},{%0,%1,%2,%3};\n"
                        : "+f"(acc[mt][nt][0]), "+f"(acc[mt][nt][1]),
                          "+f"(acc[mt][nt][2]), "+f"(acc[mt][nt][3])
                        : "r"(af[mt][0]), "r"(af[mt][1]), "r"(af[mt][2]), "r"(af[mt][3]),
                          "r"(bf[nt][0]), "r"(bf[nt][1]));
                }
        }
    }

    // epilogue: bias (+ optional mish), float2 stores
    #pragma unroll
    for (int mt = 0; mt < 2; mt++) {
        #pragma unroll
        for (int nt = 0; nt < 4; nt++) {
            size_t r0 = bm + wm + mt * 16 + (lane >> 2);
            int    c0 = bn + wn + nt * 8 + (lane & 3) * 2;
            float bv0 = bias[c0], bv1 = bias[c0 + 1];
            float v0 = acc[mt][nt][0] + bv0;
            float v1 = acc[mt][nt][1] + bv1;
            float v2 = acc[mt][nt][2] + bv0;
            float v3 = acc[mt][nt][3] + bv1;
            if (MISH) { v0 = mish_f(v0); v1 = mish_f(v1); v2 = mish_f(v2); v3 = mish_f(v3); }
            *reinterpret_cast<float2*>(C + r0 * ND + c0)       = make_float2(v0, v1);
            *reinterpret_cast<float2*>(C + (r0 + 8) * ND + c0) = make_float2(v2, v3);
        }
    }
}

// ============================================================
// Kernel 6: out[b,m,:] = LayerNorm(x[b,m,:] + P[b,m/4,:] + S[b,:])
// One CTA (128 threads) per output row.
// ============================================================
__global__ void ln_kernel(const float* __restrict__ x,
                          const float* __restrict__ gamma,
                          const float* __restrict__ beta,
                          float* __restrict__ out)
{
    const int row  = blockIdx.x;          // b*96 + m
    const int b    = row / NCELLS;
    const int m    = row - b * NCELLS;
    const int line = m >> 2;
    const int t    = threadIdx.x;         // 0..127

    const float4* xr = reinterpret_cast<const float4*>(x) + (size_t)row * (ND/4) + t;
    const float4* pr = reinterpret_cast<const float4*>(g_P) + ((size_t)b * NLINES + line) * (ND/4) + t;
    const float4* sr = reinterpret_cast<const float4*>(g_S) + (size_t)b * (ND/4) + t;

    float4 xv = *xr, pv = *pr, sv = *sr;
    float4 v = make_float4(xv.x + pv.x + sv.x, xv.y + pv.y + sv.y,
                           xv.z + pv.z + sv.z, xv.w + pv.w + sv.w);

    float s  = v.x + v.y + v.z + v.w;
    float sq = v.x*v.x + v.y*v.y + v.z*v.z + v.w*v.w;
    #pragma unroll
    for (int o = 16; o; o >>= 1) {
        s  += __shfl_xor_sync(0xffffffffu, s,  o);
        sq += __shfl_xor_sync(0xffffffffu, sq, o);
    }
    __shared__ float sh[8];
    const int w = t >> 5, ln_id = t & 31;
    if (ln_id == 0) { sh[w] = s; sh[4 + w] = sq; }
    __syncthreads();
    s  = sh[0] + sh[1] + sh[2] + sh[3];
    sq = sh[4] + sh[5] + sh[6] + sh[7];

    const float mean = s * (1.0f / ND);
    const float var  = sq * (1.0f / ND) - mean * mean;
    const float inv  = rsqrtf(var + 1e-5f);

    float4 gv = reinterpret_cast<const float4*>(gamma)[t];
    float4 bv = reinterpret_cast<const float4*>(beta)[t];
    float4 o;
    o.x = (v.x - mean) * inv * gv.x + bv.x;
    o.y = (v.y - mean) * inv * gv.y + bv.y;
    o.z = (v.z - mean) * inv * gv.z + bv.z;
    o.w = (v.w - mean) * inv * gv.w + bv.w;
    reinterpret_cast<float4*>(out)[(size_t)row * (ND/4) + t] = o;
}

// ============================================================
// launch
// ============================================================
extern "C" void kernel_launch(void* const* d_in, const int* in_sizes, int n_in,
                              void* d_out, int out_size)
{
    const float* x     = (const float*)d_in[0];
    // d_in[1] = M (block-diagonal, structure hardcoded)
    const float* W1    = (const float*)d_in[2];
    const float* b1    = (const float*)d_in[3];
    const float* W2    = (const float*)d_in[4];
    const float* b2    = (const float*)d_in[5];
    const float* G1    = (const float*)d_in[6];
    const float* gb1   = (const float*)d_in[7];
    const float* G2    = (const float*)d_in[8];
    const float* gb2   = (const float*)d_in[9];
    const float* gamma = (const float*)d_in[10];
    const float* beta  = (const float*)d_in[11];
    float* out = (float*)d_out;

    float *pLC, *pGC, *pH, *pP, *pHg, *pS;
    cudaGetSymbolAddress((void**)&pLC, g_LC);
    cudaGetSymbolAddress((void**)&pGC, g_GC);
    cudaGetSymbolAddress((void**)&pH,  g_H);
    cudaGetSymbolAddress((void**)&pP,  g_P);
    cudaGetSymbolAddress((void**)&pHg, g_Hg);
    cudaGetSymbolAddress((void**)&pS,  g_S);

    // 1) gather reductions
    reduce_kernel<<<NB, 128>>>(x);

    // 2) line MLP: H = mish(LC @ W1 + b1) ; P = H @ W2 + b2
    gemm_kernel<true ><<<dim3(NROWS / 128, 8), 256>>>(pLC, W1, b1, pH);
    gemm_kernel<false><<<dim3(NROWS / 128, 8), 256>>>(pH,  W2, b2, pP);

    // 3) global MLP: Hg = mish(GC @ G1 + gb1) ; S = Hg @ G2 + gb2
    gemm_kernel<true ><<<dim3(NB / 128, 8), 256>>>(pGC, G1, gb1, pHg);
    gemm_kernel<false><<<dim3(NB / 128, 8), 256>>>(pHg, G2, gb2, pS);

    // 4) combine + LayerNorm
    ln_kernel<<<NB * NCELLS, 128>>>(x, gamma, beta, out);
}

// round 3
// speedup vs baseline: 1.0808x; 1.0808x over previous
#include <cuda_runtime.h>
#include <cuda_fp16.h>
#include <cstdint>

#define NB     2048
#define NCELLS 96
#define NLINES 24
#define ND     512
#define NROWS  (NB * NLINES)   // 49152

// -------- scratch (device globals; allocation-free) --------
__device__ __align__(16) __half g_LC[(size_t)NROWS * ND];
__device__ __align__(16) __half g_GC[(size_t)NB * ND];
__device__ __align__(16) __half g_H [(size_t)NROWS * ND];
__device__ __align__(16) float  g_P [(size_t)NROWS * ND];
__device__ __align__(16) __half g_Hg[(size_t)NB * ND];
__device__ __align__(16) float  g_S [(size_t)NB * ND];
__device__ __align__(16) __half g_Wt[4][(size_t)ND * ND];   // W1,W2,G1,G2 transposed [n][k], fp16

// ============================================================
// Weight convert+transpose: W fp32 [k][n] -> Wt fp16 [n][k]
// ============================================================
__global__ void wconv_kernel(const float* __restrict__ W, __half* __restrict__ Wt)
{
    __shared__ float tile[32][33];
    const int k0 = blockIdx.y * 32, n0 = blockIdx.x * 32;
    #pragma unroll
    for (int i = threadIdx.y; i < 32; i += 8)
        tile[i][threadIdx.x] = W[(size_t)(k0 + i) * ND + n0 + threadIdx.x];
    __syncthreads();
    #pragma unroll
    for (int i = threadIdx.y; i < 32; i += 8)
        Wt[(size_t)(n0 + i) * ND + k0 + threadIdx.x] = __float2half(tile[threadIdx.x][i]);
}

// ============================================================
// Kernel 1: per-batch reduction -> fp16 outputs
// LC[b,l,:] = mean of 4 cells; GC[b,:] = mean of 96 cells
// ============================================================
__global__ void reduce_kernel(const float* __restrict__ x)
{
    const int b = blockIdx.x;
    const int t = threadIdx.x;                       // 0..127, owns 4 d's
    const float4* xr = reinterpret_cast<const float4*>(x) + (size_t)b * NCELLS * (ND/4) + t;

    float tx = 0.f, ty = 0.f, tz = 0.f, tw = 0.f;
    #pragma unroll 4
    for (int g = 0; g < NLINES; g++) {
        float4 v0 = xr[(g*4 + 0) * (ND/4)];
        float4 v1 = xr[(g*4 + 1) * (ND/4)];
        float4 v2 = xr[(g*4 + 2) * (ND/4)];
        float4 v3 = xr[(g*4 + 3) * (ND/4)];
        float sx = v0.x + v1.x + v2.x + v3.x;
        float sy = v0.y + v1.y + v2.y + v3.y;
        float sz = v0.z + v1.z + v2.z + v3.z;
        float sw = v0.w + v1.w + v2.w + v3.w;
        __half2 lo = __floats2half2_rn(sx * 0.25f, sy * 0.25f);
        __half2 hi = __floats2half2_rn(sz * 0.25f, sw * 0.25f);
        uint2 pk = make_uint2(*(uint32_t*)&lo, *(uint32_t*)&hi);
        *reinterpret_cast<uint2*>(&g_LC[((size_t)b * NLINES + g) * ND + t * 4]) = pk;
        tx += sx; ty += sy; tz += sz; tw += sw;
    }
    const float inv96 = 1.0f / 96.0f;
    __half2 lo = __floats2half2_rn(tx * inv96, ty * inv96);
    __half2 hi = __floats2half2_rn(tz * inv96, tw * inv96);
    uint2 pk = make_uint2(*(uint32_t*)&lo, *(uint32_t*)&hi);
    *reinterpret_cast<uint2*>(&g_GC[(size_t)b * ND + t * 4]) = pk;
}

// ============================================================
// FP16 GEMM: C[M,512] = act(A[M,512] @ Wt^T + bias)
// A fp16 row-major [m][k]; Wt fp16 [n][k] (pre-transposed).
// BM=128 BN=128 BK=32, 3-stage cp.async, 256 threads,
// 8 warps (4m x 2n), warp tile 32x64, mma.m16n8k16.f16.
// MISH=true  -> mish epilogue, fp16 output
// MISH=false -> plain bias,   fp32 output
// ============================================================
__device__ __forceinline__ float mish_f(float v)
{
    float sp = log1pf(expf(v));
    return v * tanhf(sp);
}

#define SPAD   40                 // 32 + 8 halfs pad: conflict-free half2 frag loads
#define STAGEB (128 * SPAD * 2)   // bytes per stage per operand

template<bool MISH>
__global__ void __launch_bounds__(256)
gemm_h_kernel(const __half* __restrict__ A, const __half* __restrict__ Bt,
              const float* __restrict__ bias, void* __restrict__ Cout)
{
    extern __shared__ __half smem[];
    __half (*As)[128][SPAD] = reinterpret_cast<__half(*)[128][SPAD]>(smem);
    __half (*Bs)[128][SPAD] = reinterpret_cast<__half(*)[128][SPAD]>(smem + 3 * 128 * SPAD);

    const int tid  = threadIdx.x;
    const int lane = tid & 31;
    const int warp = tid >> 5;
    const int wm = (warp >> 1) * 32;   // 4 warps over M
    const int wn = (warp & 1) * 64;    // 2 warps over N

    const size_t bm = (size_t)blockIdx.x * 128;
    const int    bn = blockIdx.y * 128;

    // global->shared mapping: thread handles row tid>>1, 32B at halfs (tid&1)*16
    const int lrow = tid >> 1;
    const int lcol = (tid & 1) * 16;
    const __half* gA = A  + (bm + lrow) * (size_t)ND + lcol;
    const __half* gB = Bt + (size_t)(bn + lrow) * ND + lcol;
    const uint32_t sA = (uint32_t)__cvta_generic_to_shared(&As[0][lrow][lcol]);
    const uint32_t sB = (uint32_t)__cvta_generic_to_shared(&Bs[0][lrow][lcol]);

    auto issue = [&](int kt, int buf) {
        const __half* pa = gA + kt * 32;
        const __half* pb = gB + kt * 32;
        uint32_t da = sA + buf * STAGEB;
        uint32_t db = sB + buf * STAGEB;
        asm volatile("cp.async.cg.shared.global [%0],[%1],16;\n" :: "r"(da),      "l"(pa));
        asm volatile("cp.async.cg.shared.global [%0],[%1],16;\n" :: "r"(da + 16), "l"(pa + 8));
        asm volatile("cp.async.cg.shared.global [%0],[%1],16;\n" :: "r"(db),      "l"(pb));
        asm volatile("cp.async.cg.shared.global [%0],[%1],16;\n" :: "r"(db + 16), "l"(pb + 8));
    };

    float acc[2][8][4];
    #pragma unroll
    for (int mt = 0; mt < 2; mt++)
        #pragma unroll
        for (int nt = 0; nt < 8; nt++)
            #pragma unroll
            for (int k = 0; k < 4; k++) acc[mt][nt][k] = 0.f;

    issue(0, 0); asm volatile("cp.async.commit_group;\n" ::);
    issue(1, 1); asm volatile("cp.async.commit_group;\n" ::);

    const int fr = lane >> 2;          // 0..7
    const int fc = (lane & 3) * 2;     // 0,2,4,6

    for (int i = 0; i < 16; i++) {
        asm volatile("cp.async.wait_group 1;\n" ::);
        __syncthreads();
        if (i + 2 < 16) issue(i + 2, (i + 2) % 3);
        asm volatile("cp.async.commit_group;\n" ::);
        const int buf = i % 3;

        #pragma unroll
        for (int ks = 0; ks < 32; ks += 16) {
            uint32_t a[2][4], b[8][2];
            #pragma unroll
            for (int mt = 0; mt < 2; mt++) {
                const int r = wm + mt * 16 + fr;
                const int c = ks + fc;
                a[mt][0] = *(const uint32_t*)&As[buf][r    ][c    ];
                a[mt][1] = *(const uint32_t*)&As[buf][r + 8][c    ];
                a[mt][2] = *(const uint32_t*)&As[buf][r    ][c + 8];
                a[mt][3] = *(const uint32_t*)&As[buf][r + 8][c + 8];
            }
            #pragma unroll
            for (int nt = 0; nt < 8; nt++) {
                const int n = wn + nt * 8 + fr;
                const int c = ks + fc;
                b[nt][0] = *(const uint32_t*)&Bs[buf][n][c    ];
                b[nt][1] = *(const uint32_t*)&Bs[buf][n][c + 8];
            }
            #pragma unroll
            for (int mt = 0; mt < 2; mt++)
                #pragma unroll
                for (int nt = 0; nt < 8; nt++) {
                    asm volatile(
                        "mma.sync.aligned.m16n8k16.row.col.f32.f16.f16.f32 "
                        "{%0,%1,%2,%3},{%4,%5,%6,%7},{%8,%9},{%0,%1,%2,%3};\n"
                        : "+f"(acc[mt][nt][0]), "+f"(acc[mt][nt][1]),
                          "+f"(acc[mt][nt][2]), "+f"(acc[mt][nt][3])
                        : "r"(a[mt][0]), "r"(a[mt][1]), "r"(a[mt][2]), "r"(a[mt][3]),
                          "r"(b[nt][0]), "r"(b[nt][1]));
                }
        }
    }

    // epilogue
    #pragma unroll
    for (int mt = 0; mt < 2; mt++) {
        #pragma unroll
        for (int nt = 0; nt < 8; nt++) {
            const size_t r0 = bm + wm + mt * 16 + fr;
            const int    c0 = bn + wn + nt * 8 + fc;
            const float bv0 = bias[c0], bv1 = bias[c0 + 1];
            float v0 = acc[mt][nt][0] + bv0;
            float v1 = acc[mt][nt][1] + bv1;
            float v2 = acc[mt][nt][2] + bv0;
            float v3 = acc[mt][nt][3] + bv1;
            if (MISH) {
                v0 = mish_f(v0); v1 = mish_f(v1); v2 = mish_f(v2); v3 = mish_f(v3);
                __half* C = (__half*)Cout;
                __half2 h01 = __floats2half2_rn(v0, v1);
                __half2 h23 = __floats2half2_rn(v2, v3);
                *reinterpret_cast<__half2*>(&C[r0 * ND + c0])       = h01;
                *reinterpret_cast<__half2*>(&C[(r0 + 8) * ND + c0]) = h23;
            } else {
                float* C = (float*)Cout;
                *reinterpret_cast<float2*>(&C[r0 * ND + c0])       = make_float2(v0, v1);
                *reinterpret_cast<float2*>(&C[(r0 + 8) * ND + c0]) = make_float2(v2, v3);
            }
        }
    }
}

// ============================================================
// Kernel 6: out[b,m,:] = LayerNorm(x[b,m,:] + P[b,m/4,:] + S[b,:])
// ============================================================
__global__ void ln_kernel(const float* __restrict__ x,
                          const float* __restrict__ gamma,
                          const float* __restrict__ beta,
                          float* __restrict__ out)
{
    const int row  = blockIdx.x;          // b*96 + m
    const int b    = row / NCELLS;
    const int m    = row - b * NCELLS;
    const int line = m >> 2;
    const int t    = threadIdx.x;         // 0..127

    const float4* xr = reinterpret_cast<const float4*>(x) + (size_t)row * (ND/4) + t;
    const float4* pr = reinterpret_cast<const float4*>(g_P) + ((size_t)b * NLINES + line) * (ND/4) + t;
    const float4* sr = reinterpret_cast<const float4*>(g_S) + (size_t)b * (ND/4) + t;

    float4 xv = *xr, pv = *pr, sv = *sr;
    float4 v = make_float4(xv.x + pv.x + sv.x, xv.y + pv.y + sv.y,
                           xv.z + pv.z + sv.z, xv.w + pv.w + sv.w);

    float s  = v.x + v.y + v.z + v.w;
    float sq = v.x*v.x + v.y*v.y + v.z*v.z + v.w*v.w;
    #pragma unroll
    for (int o = 16; o; o >>= 1) {
        s  += __shfl_xor_sync(0xffffffffu, s,  o);
        sq += __shfl_xor_sync(0xffffffffu, sq, o);
    }
    __shared__ float sh[8];
    const int w = t >> 5, ln_id = t & 31;
    if (ln_id == 0) { sh[w] = s; sh[4 + w] = sq; }
    __syncthreads();
    s  = sh[0] + sh[1] + sh[2] + sh[3];
    sq = sh[4] + sh[5] + sh[6] + sh[7];

    const float mean = s * (1.0f / ND);
    const float var  = sq * (1.0f / ND) - mean * mean;
    const float inv  = rsqrtf(var + 1e-5f);

    float4 gv = reinterpret_cast<const float4*>(gamma)[t];
    float4 bv = reinterpret_cast<const float4*>(beta)[t];
    float4 o;
    o.x = (v.x - mean) * inv * gv.x + bv.x;
    o.y = (v.y - mean) * inv * gv.y + bv.y;
    o.z = (v.z - mean) * inv * gv.z + bv.z;
    o.w = (v.w - mean) * inv * gv.w + bv.w;
    reinterpret_cast<float4*>(out)[(size_t)row * (ND/4) + t] = o;
}

// ============================================================
// launch
// ============================================================
extern "C" void kernel_launch(void* const* d_in, const int* in_sizes, int n_in,
                              void* d_out, int out_size)
{
    const float* x     = (const float*)d_in[0];
    const float* W1    = (const float*)d_in[2];
    const float* b1    = (const float*)d_in[3];
    const float* W2    = (const float*)d_in[4];
    const float* b2    = (const float*)d_in[5];
    const float* G1    = (const float*)d_in[6];
    const float* gb1   = (const float*)d_in[7];
    const float* G2    = (const float*)d_in[8];
    const float* gb2   = (const float*)d_in[9];
    const float* gamma = (const float*)d_in[10];
    const float* beta  = (const float*)d_in[11];
    float* out = (float*)d_out;

    __half *pLC, *pGC, *pH, *pHg, *pWt;
    float  *pP, *pS;
    cudaGetSymbolAddress((void**)&pLC, g_LC);
    cudaGetSymbolAddress((void**)&pGC, g_GC);
    cudaGetSymbolAddress((void**)&pH,  g_H);
    cudaGetSymbolAddress((void**)&pP,  g_P);
    cudaGetSymbolAddress((void**)&pHg, g_Hg);
    cudaGetSymbolAddress((void**)&pS,  g_S);
    cudaGetSymbolAddress((void**)&pWt, g_Wt);
    __half* pW1t = pWt + 0 * (size_t)ND * ND;
    __half* pW2t = pWt + 1 * (size_t)ND * ND;
    __half* pG1t = pWt + 2 * (size_t)ND * ND;
    __half* pG2t = pWt + 3 * (size_t)ND * ND;

    const int smemB = 3 * 128 * SPAD * 2 * 2;   // 61440
    cudaFuncSetAttribute(gemm_h_kernel<true >, cudaFuncAttributeMaxDynamicSharedMemorySize, smemB);
    cudaFuncSetAttribute(gemm_h_kernel<false>, cudaFuncAttributeMaxDynamicSharedMemorySize, smemB);

    dim3 wgrid(16, 16), wblk(32, 8);
    wconv_kernel<<<wgrid, wblk>>>(W1, pW1t);
    wconv_kernel<<<wgrid, wblk>>>(W2, pW2t);
    wconv_kernel<<<wgrid, wblk>>>(G1, pG1t);
    wconv_kernel<<<wgrid, wblk>>>(G2, pG2t);

    reduce_kernel<<<NB, 128>>>(x);

    gemm_h_kernel<true ><<<dim3(NROWS / 128, 4), 256, smemB>>>(pLC, pW1t, b1, pH);
    gemm_h_kernel<false><<<dim3(NROWS / 128, 4), 256, smemB>>>(pH,  pW2t, b2, pP);

    gemm_h_kernel<true ><<<dim3(NB / 128, 4), 256, smemB>>>(pGC, pG1t, gb1, pHg);
    gemm_h_kernel<false><<<dim3(NB / 128, 4), 256, smemB>>>(pHg, pG2t, gb2, pS);

    ln_kernel<<<NB * NCELLS, 128>>>(x, gamma, beta, out);
}

// round 6
// speedup vs baseline: 1.8061x; 1.6710x over previous
#include <cuda_runtime.h>
#include <cuda_fp16.h>
#include <cstdint>

#define NB     2048
#define NCELLS 96
#define NLINES 24
#define ND     512
#define NROWS  (NB * NLINES)   // 49152

// -------- scratch (device globals; allocation-free) --------
__device__ __align__(1024) __half g_LC[(size_t)NROWS * ND];
__device__ __align__(1024) __half g_GC[(size_t)NB * ND];
__device__ __align__(1024) __half g_H [(size_t)NROWS * ND];
__device__ __align__(1024) float  g_P [(size_t)NROWS * ND];
__device__ __align__(1024) __half g_Hg[(size_t)NB * ND];
__device__ __align__(1024) float  g_S [(size_t)NB * ND];
__device__ __align__(1024) __half g_Wt[4][(size_t)ND * ND];   // W1,W2,G1,G2 transposed [n][k] fp16

// ============================================================
// Weight convert+transpose (all 4 weights, one launch):
// W fp32 [k][n] -> Wt fp16 [n][k]
// ============================================================
__global__ void wconv_all_kernel(const float* __restrict__ W1, const float* __restrict__ W2,
                                 const float* __restrict__ G1, const float* __restrict__ G2)
{
    __shared__ float tile[32][33];
    const float* W = (blockIdx.z == 0) ? W1 : (blockIdx.z == 1) ? W2 :
                     (blockIdx.z == 2) ? G1 : G2;
    __half* Wt = &g_Wt[blockIdx.z][0];
    const int k0 = blockIdx.y * 32, n0 = blockIdx.x * 32;
    #pragma unroll
    for (int i = threadIdx.y; i < 32; i += 8)
        tile[i][threadIdx.x] = W[(size_t)(k0 + i) * ND + n0 + threadIdx.x];
    __syncthreads();
    #pragma unroll
    for (int i = threadIdx.y; i < 32; i += 8)
        Wt[(size_t)(n0 + i) * ND + k0 + threadIdx.x] = __float2half(tile[threadIdx.x][i]);
}

// ============================================================
// Kernel 1: per-batch reduction -> fp16 LC / GC
// ============================================================
__global__ void reduce_kernel(const float* __restrict__ x)
{
    const int b = blockIdx.x;
    const int t = threadIdx.x;                       // 0..127
    const float4* xr = reinterpret_cast<const float4*>(x) + (size_t)b * NCELLS * (ND/4) + t;

    float tx = 0.f, ty = 0.f, tz = 0.f, tw = 0.f;
    #pragma unroll 4
    for (int g = 0; g < NLINES; g++) {
        float4 v0 = xr[(g*4 + 0) * (ND/4)];
        float4 v1 = xr[(g*4 + 1) * (ND/4)];
        float4 v2 = xr[(g*4 + 2) * (ND/4)];
        float4 v3 = xr[(g*4 + 3) * (ND/4)];
        float sx = v0.x + v1.x + v2.x + v3.x;
        float sy = v0.y + v1.y + v2.y + v3.y;
        float sz = v0.z + v1.z + v2.z + v3.z;
        float sw = v0.w + v1.w + v2.w + v3.w;
        __half2 lo = __floats2half2_rn(sx * 0.25f, sy * 0.25f);
        __half2 hi = __floats2half2_rn(sz * 0.25f, sw * 0.25f);
        uint2 pk = make_uint2(*(uint32_t*)&lo, *(uint32_t*)&hi);
        *reinterpret_cast<uint2*>(&g_LC[((size_t)b * NLINES + g) * ND + t * 4]) = pk;
        tx += sx; ty += sy; tz += sz; tw += sw;
    }
    const float inv96 = 1.0f / 96.0f;
    __half2 lo = __floats2half2_rn(tx * inv96, ty * inv96);
    __half2 hi = __floats2half2_rn(tz * inv96, tw * inv96);
    uint2 pk = make_uint2(*(uint32_t*)&lo, *(uint32_t*)&hi);
    *reinterpret_cast<uint2*>(&g_GC[(size_t)b * ND + t * 4]) = pk;
}

// ============================================================
// FP16 GEMM with ldmatrix: C[M,512] = act(A[M,512] @ Bt^T + bias)
// BM=128 BN=128 BK=32, 3-stage cp.async, 256 threads,
// 8 warps (4m x 2n), warp tile 32x64, m16n8k16, ldmatrix.x4 frags.
// Two independent problems dispatched in one launch (blockIdx.x split).
// ============================================================
__device__ __forceinline__ float mish_f(float v)
{
    float sp = log1pf(expf(v));
    return v * tanhf(sp);
}

#define SPAD    40                        // halfs per row (32 data + 8 pad) -> 80B stride
#define TILE_H  (128 * SPAD)              // halfs per operand per stage
#define STAGE_H (2 * TILE_H)              // A then B
#define NSTAGE  3
#define SMEM_HALFS (NSTAGE * STAGE_H)     // 30720 halfs = 61440 B

#define LDMX4(r0, r1, r2, r3, addr) \
    asm volatile("ldmatrix.sync.aligned.m8n8.x4.shared.b16 {%0,%1,%2,%3}, [%4];" \
                 : "=r"(r0), "=r"(r1), "=r"(r2), "=r"(r3) : "r"(addr))

template<bool MISH>
__global__ void __launch_bounds__(256)
gemm_kernel(const __half* __restrict__ A0, const __half* __restrict__ B0,
            const float* __restrict__ bias0, void* __restrict__ C0, int mb0,
            const __half* __restrict__ A1, const __half* __restrict__ B1,
            const float* __restrict__ bias1, void* __restrict__ C1)
{
    extern __shared__ __half smem[];

    const __half* A;  const __half* Bt;  const float* bias;  void* Cout;
    size_t bm;
    if ((int)blockIdx.x < mb0) { A = A0; Bt = B0; bias = bias0; Cout = C0; bm = (size_t)blockIdx.x * 128; }
    else                       { A = A1; Bt = B1; bias = bias1; Cout = C1; bm = (size_t)(blockIdx.x - mb0) * 128; }
    const int bn = blockIdx.y * 128;

    const int tid  = threadIdx.x;
    const int lane = tid & 31;
    const int warp = tid >> 5;
    const int wm = (warp >> 1) * 32;   // 4 warps over M
    const int wn = (warp & 1) * 64;    // 2 warps over N

    // ---- cp.async producer mapping: 512 x 16B segs per operand ----
    // seg idx: row = idx>>2 (0..127), seg = idx&3 (16B each of 64B row)
    const uint32_t sbase = (uint32_t)__cvta_generic_to_shared(smem);
    auto load_chunk = [&](int kc, int buf) {
        const uint32_t st = sbase + buf * (STAGE_H * 2);
        #pragma unroll
        for (int j = 0; j < 2; j++) {                      // A: 512 segs / 256 thr
            const int idx = tid + 256 * j;
            const int row = idx >> 2, seg = idx & 3;
            uint32_t dst = st + row * (SPAD * 2) + seg * 16;
            const __half* src = A + (bm + row) * (size_t)ND + kc * 32 + seg * 8;
            asm volatile("cp.async.cg.shared.global [%0],[%1],16;\n" :: "r"(dst), "l"(src));
        }
        #pragma unroll
        for (int j = 0; j < 2; j++) {                      // B
            const int idx = tid + 256 * j;
            const int row = idx >> 2, seg = idx & 3;
            uint32_t dst = st + (TILE_H * 2) + row * (SPAD * 2) + seg * 16;
            const __half* src = Bt + (size_t)(bn + row) * ND + kc * 32 + seg * 8;
            asm volatile("cp.async.cg.shared.global [%0],[%1],16;\n" :: "r"(dst), "l"(src));
        }
        asm volatile("cp.async.commit_group;\n" ::);
    };

    // ---- ldmatrix lane address offsets (bytes, within a stage) ----
    // A (mt in 0..1): row = wm + mt*16 + (lane&15), col base = (lane>>4)*8
    // B (pair in 0..3): row = wn + pair*16 + ((lane>>4)<<3) + (lane&7), col base = ((lane>>3)&1)*8
    uint32_t aoff[2], boff[4];
    #pragma unroll
    for (int mt = 0; mt < 2; mt++)
        aoff[mt] = (wm + mt * 16 + (lane & 15)) * (SPAD * 2) + ((lane >> 4) * 8) * 2;
    #pragma unroll
    for (int p = 0; p < 4; p++)
        boff[p] = (TILE_H * 2) +
                  (wn + p * 16 + ((lane >> 4) << 3) + (lane & 7)) * (SPAD * 2) +
                  (((lane >> 3) & 1) * 8) * 2;

    float acc[2][8][4];
    #pragma unroll
    for (int mt = 0; mt < 2; mt++)
        #pragma unroll
        for (int nt = 0; nt < 8; nt++)
            #pragma unroll
            for (int k = 0; k < 4; k++) acc[mt][nt][k] = 0.f;

    load_chunk(0, 0);
    load_chunk(1, 1);

    for (int i = 0; i < 16; i++) {
        asm volatile("cp.async.wait_group 1;\n" ::);
        __syncthreads();
        if (i + 2 < 16) load_chunk(i + 2, (i + 2) % 3);
        else            asm volatile("cp.async.commit_group;\n" ::);
        const uint32_t st = sbase + (i % 3) * (STAGE_H * 2);

        #pragma unroll
        for (int ks = 0; ks < 32; ks += 16) {
            uint32_t a[2][4], b[4][4];
            #pragma unroll
            for (int mt = 0; mt < 2; mt++)
                LDMX4(a[mt][0], a[mt][1], a[mt][2], a[mt][3], st + aoff[mt] + ks * 2);
            #pragma unroll
            for (int p = 0; p < 4; p++)
                LDMX4(b[p][0], b[p][1], b[p][2], b[p][3], st + boff[p] + ks * 2);

            #pragma unroll
            for (int mt = 0; mt < 2; mt++)
                #pragma unroll
                for (int p = 0; p < 4; p++) {
                    asm volatile(
                        "mma.sync.aligned.m16n8k16.row.col.f32.f16.f16.f32 "
                        "{%0,%1,%2,%3},{%4,%5,%6,%7},{%8,%9},{%0,%1,%2,%3};\n"
                        : "+f"(acc[mt][2*p][0]), "+f"(acc[mt][2*p][1]),
                          "+f"(acc[mt][2*p][2]), "+f"(acc[mt][2*p][3])
                        : "r"(a[mt][0]), "r"(a[mt][1]), "r"(a[mt][2]), "r"(a[mt][3]),
                          "r"(b[p][0]), "r"(b[p][1]));
                    asm volatile(
                        "mma.sync.aligned.m16n8k16.row.col.f32.f16.f16.f32 "
                        "{%0,%1,%2,%3},{%4,%5,%6,%7},{%8,%9},{%0,%1,%2,%3};\n"
                        : "+f"(acc[mt][2*p+1][0]), "+f"(acc[mt][2*p+1][1]),
                          "+f"(acc[mt][2*p+1][2]), "+f"(acc[mt][2*p+1][3])
                        : "r"(a[mt][0]), "r"(a[mt][1]), "r"(a[mt][2]), "r"(a[mt][3]),
                          "r"(b[p][2]), "r"(b[p][3]));
                }
        }
    }

    // ---- epilogue ----
    const int fr = lane >> 2;          // 0..7
    const int fc = (lane & 3) * 2;     // 0,2,4,6
    #pragma unroll
    for (int mt = 0; mt < 2; mt++) {
        #pragma unroll
        for (int nt = 0; nt < 8; nt++) {
            const size_t r0 = bm + wm + mt * 16 + fr;
            const int    c0 = bn + wn + nt * 8 + fc;
            const float bv0 = bias[c0], bv1 = bias[c0 + 1];
            float v0 = acc[mt][nt][0] + bv0;
            float v1 = acc[mt][nt][1] + bv1;
            float v2 = acc[mt][nt][2] + bv0;
            float v3 = acc[mt][nt][3] + bv1;
            if (MISH) {
                v0 = mish_f(v0); v1 = mish_f(v1); v2 = mish_f(v2); v3 = mish_f(v3);
                __half* C = (__half*)Cout;
                *reinterpret_cast<__half2*>(&C[r0 * ND + c0])       = __floats2half2_rn(v0, v1);
                *reinterpret_cast<__half2*>(&C[(r0 + 8) * ND + c0]) = __floats2half2_rn(v2, v3);
            } else {
                float* C = (float*)Cout;
                *reinterpret_cast<float2*>(&C[r0 * ND + c0])       = make_float2(v0, v1);
                *reinterpret_cast<float2*>(&C[(r0 + 8) * ND + c0]) = make_float2(v2, v3);
            }
        }
    }
}

// ============================================================
// LN: out[b,m,:] = LayerNorm(x[b,m,:] + P[b,m/4,:] + S[b,:])
// Warp per row: no smem, no CTA barrier, MLP=4 float4/thread.
// ============================================================
__global__ void __launch_bounds__(256)
ln_kernel(const float* __restrict__ x,
          const float* __restrict__ gamma,
          const float* __restrict__ beta,
          float* __restrict__ out)
{
    const int warp = threadIdx.x >> 5;
    const int lane = threadIdx.x & 31;
    const int row  = blockIdx.x * 8 + warp;      // b*96 + m
    const int b    = row / NCELLS;
    const int m    = row - b * NCELLS;
    const int line = m >> 2;

    const float4* xr = reinterpret_cast<const float4*>(x) + (size_t)row * (ND/4);
    const float4* pr = reinterpret_cast<const float4*>(g_P) + ((size_t)b * NLINES + line) * (ND/4);
    const float4* sr = reinterpret_cast<const float4*>(g_S) + (size_t)b * (ND/4);

    float4 v[4];
    float s = 0.f, sq = 0.f;
    #pragma unroll
    for (int j = 0; j < 4; j++) {
        const int t = lane + j * 32;
        float4 xv = xr[t], pv = pr[t], sv = sr[t];
        float4 w = make_float4(xv.x + pv.x + sv.x, xv.y + pv.y + sv.y,
                               xv.z + pv.z + sv.z, xv.w + pv.w + sv.w);
        v[j] = w;
        s  += w.x + w.y + w.z + w.w;
        sq += w.x*w.x + w.y*w.y + w.z*w.z + w.w*w.w;
    }
    #pragma unroll
    for (int o = 16; o; o >>= 1) {
        s  += __shfl_xor_sync(0xffffffffu, s,  o);
        sq += __shfl_xor_sync(0xffffffffu, sq, o);
    }
    const float mean = s * (1.0f / ND);
    const float var  = sq * (1.0f / ND) - mean * mean;
    const float inv  = rsqrtf(var + 1e-5f);

    float4* orow = reinterpret_cast<float4*>(out) + (size_t)row * (ND/4);
    #pragma unroll
    for (int j = 0; j < 4; j++) {
        const int t = lane + j * 32;
        float4 gv = reinterpret_cast<const float4*>(gamma)[t];
        float4 bv = reinterpret_cast<const float4*>(beta)[t];
        float4 o;
        o.x = (v[j].x - mean) * inv * gv.x + bv.x;
        o.y = (v[j].y - mean) * inv * gv.y + bv.y;
        o.z = (v[j].z - mean) * inv * gv.z + bv.z;
        o.w = (v[j].w - mean) * inv * gv.w + bv.w;
        orow[t] = o;
    }
}

// ============================================================
// launch
// ============================================================
extern "C" void kernel_launch(void* const* d_in, const int* in_sizes, int n_in,
                              void* d_out, int out_size)
{
    const float* x     = (const float*)d_in[0];
    const float* W1    = (const float*)d_in[2];
    const float* b1    = (const float*)d_in[3];
    const float* W2    = (const float*)d_in[4];
    const float* b2    = (const float*)d_in[5];
    const float* G1    = (const float*)d_in[6];
    const float* gb1   = (const float*)d_in[7];
    const float* G2    = (const float*)d_in[8];
    const float* gb2   = (const float*)d_in[9];
    const float* gamma = (const float*)d_in[10];
    const float* beta  = (const float*)d_in[11];
    float* out = (float*)d_out;

    __half *pLC, *pGC, *pH, *pHg, *pWt;
    float  *pP, *pS;
    cudaGetSymbolAddress((void**)&pLC, g_LC);
    cudaGetSymbolAddress((void**)&pGC, g_GC);
    cudaGetSymbolAddress((void**)&pH,  g_H);
    cudaGetSymbolAddress((void**)&pP,  g_P);
    cudaGetSymbolAddress((void**)&pHg, g_Hg);
    cudaGetSymbolAddress((void**)&pS,  g_S);
    cudaGetSymbolAddress((void**)&pWt, g_Wt);
    __half* pW1t = pWt + 0 * (size_t)ND * ND;
    __half* pW2t = pWt + 1 * (size_t)ND * ND;
    __half* pG1t = pWt + 2 * (size_t)ND * ND;
    __half* pG2t = pWt + 3 * (size_t)ND * ND;

    const int smemB = SMEM_HALFS * 2;   // 61440
    cudaFuncSetAttribute(gemm_kernel<true >, cudaFuncAttributeMaxDynamicSharedMemorySize, smemB);
    cudaFuncSetAttribute(gemm_kernel<false>, cudaFuncAttributeMaxDynamicSharedMemorySize, smemB);

    // 1) weights (single launch)
    wconv_all_kernel<<<dim3(16, 16, 4), dim3(32, 8)>>>(W1, W2, G1, G2);

    // 2) gather reductions
    reduce_kernel<<<NB, 128>>>(x);

    // 3) stage 1 (mish): big [LC@W1 -> H] + small [GC@G1 -> Hg] fused in one grid
    const int mb_big = NROWS / 128, mb_sm = NB / 128;   // 384, 16
    gemm_kernel<true ><<<dim3(mb_big + mb_sm, 4), 256, smemB>>>(
        pLC, pW1t, b1, pH, mb_big, pGC, pG1t, gb1, pHg);

    // 4) stage 2 (linear): big [H@W2 -> P] + small [Hg@G2 -> S]
    gemm_kernel<false><<<dim3(mb_big + mb_sm, 4), 256, smemB>>>(
        pH, pW2t, b2, pP, mb_big, pHg, pG2t, gb2, pS);

    // 5) combine + LayerNorm
    ln_kernel<<<NB * NCELLS / 8, 256>>>(x, gamma, beta, out);
}

// round 8
// speedup vs baseline: 1.9916x; 1.1027x over previous
#include <cuda_runtime.h>
#include <cuda_fp16.h>
#include <cstdint>

#define NB     2048
#define NCELLS 96
#define NLINES 24
#define ND     512
#define NROWS  (NB * NLINES)   // 49152

// -------- scratch (device globals; allocation-free) --------
__device__ __align__(1024) __half g_LC[(size_t)NROWS * ND];
__device__ __align__(1024) __half g_GC[(size_t)NB * ND];
__device__ __align__(1024) __half g_H [(size_t)NROWS * ND];
__device__ __align__(1024) __half g_P [(size_t)NROWS * ND];
__device__ __align__(1024) __half g_Hg[(size_t)NB * ND];
__device__ __align__(1024) __half g_S [(size_t)NB * ND];
__device__ __align__(1024) __half g_Wt[4][(size_t)ND * ND];   // W1,W2,G1,G2 transposed [n][k] fp16

// ============================================================
// Weight convert+transpose (all 4 weights, one launch)
// ============================================================
__global__ void wconv_all_kernel(const float* __restrict__ W1, const float* __restrict__ W2,
                                 const float* __restrict__ G1, const float* __restrict__ G2)
{
    __shared__ float tile[32][33];
    const float* W = (blockIdx.z == 0) ? W1 : (blockIdx.z == 1) ? W2 :
                     (blockIdx.z == 2) ? G1 : G2;
    __half* Wt = &g_Wt[blockIdx.z][0];
    const int k0 = blockIdx.y * 32, n0 = blockIdx.x * 32;
    #pragma unroll
    for (int i = threadIdx.y; i < 32; i += 8)
        tile[i][threadIdx.x] = W[(size_t)(k0 + i) * ND + n0 + threadIdx.x];
    __syncthreads();
    #pragma unroll
    for (int i = threadIdx.y; i < 32; i += 8)
        Wt[(size_t)(n0 + i) * ND + k0 + threadIdx.x] = __float2half(tile[threadIdx.x][i]);
}

// ============================================================
// Kernel 1: per-batch reduction -> fp16 LC / GC
// ============================================================
__global__ void reduce_kernel(const float* __restrict__ x)
{
    const int b = blockIdx.x;
    const int t = threadIdx.x;                       // 0..127
    const float4* xr = reinterpret_cast<const float4*>(x) + (size_t)b * NCELLS * (ND/4) + t;

    float tx = 0.f, ty = 0.f, tz = 0.f, tw = 0.f;
    #pragma unroll 4
    for (int g = 0; g < NLINES; g++) {
        float4 v0 = xr[(g*4 + 0) * (ND/4)];
        float4 v1 = xr[(g*4 + 1) * (ND/4)];
        float4 v2 = xr[(g*4 + 2) * (ND/4)];
        float4 v3 = xr[(g*4 + 3) * (ND/4)];
        float sx = v0.x + v1.x + v2.x + v3.x;
        float sy = v0.y + v1.y + v2.y + v3.y;
        float sz = v0.z + v1.z + v2.z + v3.z;
        float sw = v0.w + v1.w + v2.w + v3.w;
        __half2 lo = __floats2half2_rn(sx * 0.25f, sy * 0.25f);
        __half2 hi = __floats2half2_rn(sz * 0.25f, sw * 0.25f);
        uint2 pk = make_uint2(*(uint32_t*)&lo, *(uint32_t*)&hi);
        *reinterpret_cast<uint2*>(&g_LC[((size_t)b * NLINES + g) * ND + t * 4]) = pk;
        tx += sx; ty += sy; tz += sz; tw += sw;
    }
    const float inv96 = 1.0f / 96.0f;
    __half2 lo = __floats2half2_rn(tx * inv96, ty * inv96);
    __half2 hi = __floats2half2_rn(tz * inv96, tw * inv96);
    uint2 pk = make_uint2(*(uint32_t*)&lo, *(uint32_t*)&hi);
    *reinterpret_cast<uint2*>(&g_GC[(size_t)b * ND + t * 4]) = pk;
}

// ============================================================
// FP16 GEMM (ldmatrix + m16n8k16): C = act(A @ Bt^T + bias), fp16 out
// BM=128 BN=128 BK=64, 3-stage cp.async, 256 threads,
// 8 warps (4m x 2n), warp tile 32x64. Two problems per launch.
// ============================================================
__device__ __forceinline__ float mish_f(float v)
{
    float sp = log1pf(expf(v));
    return v * tanhf(sp);
}

#define BK      64
#define SPAD    72                        // 64 data + 8 pad halfs -> 144B row stride
#define TILE_H  (128 * SPAD)              // halfs per operand per stage
#define STAGE_H (2 * TILE_H)
#define NSTAGE  3
#define SMEM_B  (NSTAGE * STAGE_H * 2)    // 110592 bytes

#define LDMX4(r0, r1, r2, r3, addr) \
    asm volatile("ldmatrix.sync.aligned.m8n8.x4.shared.b16 {%0,%1,%2,%3}, [%4];" \
                 : "=r"(r0), "=r"(r1), "=r"(r2), "=r"(r3) : "r"(addr))

template<bool MISH>
__global__ void __launch_bounds__(256)
gemm_kernel(const __half* __restrict__ A0, const __half* __restrict__ B0,
            const float* __restrict__ bias0, __half* __restrict__ C0, int mb0,
            const __half* __restrict__ A1, const __half* __restrict__ B1,
            const float* __restrict__ bias1, __half* __restrict__ C1)
{
    extern __shared__ __half smem[];

    const __half* A;  const __half* Bt;  const float* bias;  __half* Cout;
    size_t bm;
    if ((int)blockIdx.x < mb0) { A = A0; Bt = B0; bias = bias0; Cout = C0; bm = (size_t)blockIdx.x * 128; }
    else                       { A = A1; Bt = B1; bias = bias1; Cout = C1; bm = (size_t)(blockIdx.x - mb0) * 128; }
    const int bn = blockIdx.y * 128;

    const int tid  = threadIdx.x;
    const int lane = tid & 31;
    const int warp = tid >> 5;
    const int wm = (warp >> 1) * 32;   // 4 warps over M
    const int wn = (warp & 1) * 64;    // 2 warps over N

    // ---- cp.async producer: per operand 128 rows x 8 segs(16B) = 1024 segs ----
    const uint32_t sbase = (uint32_t)__cvta_generic_to_shared(smem);
    auto load_chunk = [&](int kc, int buf) {
        const uint32_t st = sbase + buf * (STAGE_H * 2);
        #pragma unroll
        for (int j = 0; j < 4; j++) {                      // A
            const int idx = tid + 256 * j;
            const int row = idx >> 3, seg = idx & 7;
            uint32_t dst = st + row * (SPAD * 2) + seg * 16;
            const __half* src = A + (bm + row) * (size_t)ND + kc * BK + seg * 8;
            asm volatile("cp.async.cg.shared.global [%0],[%1],16;\n" :: "r"(dst), "l"(src));
        }
        #pragma unroll
        for (int j = 0; j < 4; j++) {                      // B
            const int idx = tid + 256 * j;
            const int row = idx >> 3, seg = idx & 7;
            uint32_t dst = st + (TILE_H * 2) + row * (SPAD * 2) + seg * 16;
            const __half* src = Bt + (size_t)(bn + row) * ND + kc * BK + seg * 8;
            asm volatile("cp.async.cg.shared.global [%0],[%1],16;\n" :: "r"(dst), "l"(src));
        }
        asm volatile("cp.async.commit_group;\n" ::);
    };

    // ---- ldmatrix lane offsets ----
    uint32_t aoff[2], boff[4];
    #pragma unroll
    for (int mt = 0; mt < 2; mt++)
        aoff[mt] = (wm + mt * 16 + (lane & 15)) * (SPAD * 2) + ((lane >> 4) * 8) * 2;
    #pragma unroll
    for (int p = 0; p < 4; p++)
        boff[p] = (TILE_H * 2) +
                  (wn + p * 16 + ((lane >> 4) << 3) + (lane & 7)) * (SPAD * 2) +
                  (((lane >> 3) & 1) * 8) * 2;

    float acc[2][8][4];
    #pragma unroll
    for (int mt = 0; mt < 2; mt++)
        #pragma unroll
        for (int nt = 0; nt < 8; nt++)
            #pragma unroll
            for (int k = 0; k < 4; k++) acc[mt][nt][k] = 0.f;

    load_chunk(0, 0);
    load_chunk(1, 1);

    for (int i = 0; i < 8; i++) {
        asm volatile("cp.async.wait_group 1;\n" ::);
        __syncthreads();
        if (i + 2 < 8) load_chunk(i + 2, (i + 2) % 3);
        else           asm volatile("cp.async.commit_group;\n" ::);
        const uint32_t st = sbase + (i % 3) * (STAGE_H * 2);

        #pragma unroll
        for (int ks = 0; ks < BK; ks += 16) {
            uint32_t a[2][4], b[4][4];
            #pragma unroll
            for (int mt = 0; mt < 2; mt++)
                LDMX4(a[mt][0], a[mt][1], a[mt][2], a[mt][3], st + aoff[mt] + ks * 2);
            #pragma unroll
            for (int p = 0; p < 4; p++)
                LDMX4(b[p][0], b[p][1], b[p][2], b[p][3], st + boff[p] + ks * 2);

            #pragma unroll
            for (int mt = 0; mt < 2; mt++)
                #pragma unroll
                for (int p = 0; p < 4; p++) {
                    asm volatile(
                        "mma.sync.aligned.m16n8k16.row.col.f32.f16.f16.f32 "
                        "{%0,%1,%2,%3},{%4,%5,%6,%7},{%8,%9},{%0,%1,%2,%3};\n"
                        : "+f"(acc[mt][2*p][0]), "+f"(acc[mt][2*p][1]),
                          "+f"(acc[mt][2*p][2]), "+f"(acc[mt][2*p][3])
                        : "r"(a[mt][0]), "r"(a[mt][1]), "r"(a[mt][2]), "r"(a[mt][3]),
                          "r"(b[p][0]), "r"(b[p][1]));
                    asm volatile(
                        "mma.sync.aligned.m16n8k16.row.col.f32.f16.f16.f32 "
                        "{%0,%1,%2,%3},{%4,%5,%6,%7},{%8,%9},{%0,%1,%2,%3};\n"
                        : "+f"(acc[mt][2*p+1][0]), "+f"(acc[mt][2*p+1][1]),
                          "+f"(acc[mt][2*p+1][2]), "+f"(acc[mt][2*p+1][3])
                        : "r"(a[mt][0]), "r"(a[mt][1]), "r"(a[mt][2]), "r"(a[mt][3]),
                          "r"(b[p][2]), "r"(b[p][3]));
                }
        }
    }

    // ---- epilogue: bias (+mish), fp16 stores ----
    const int fr = lane >> 2;
    const int fc = (lane & 3) * 2;
    #pragma unroll
    for (int mt = 0; mt < 2; mt++) {
        #pragma unroll
        for (int nt = 0; nt < 8; nt++) {
            const size_t r0 = bm + wm + mt * 16 + fr;
            const int    c0 = bn + wn + nt * 8 + fc;
            const float bv0 = bias[c0], bv1 = bias[c0 + 1];
            float v0 = acc[mt][nt][0] + bv0;
            float v1 = acc[mt][nt][1] + bv1;
            float v2 = acc[mt][nt][2] + bv0;
            float v3 = acc[mt][nt][3] + bv1;
            if (MISH) { v0 = mish_f(v0); v1 = mish_f(v1); v2 = mish_f(v2); v3 = mish_f(v3); }
            *reinterpret_cast<__half2*>(&Cout[r0 * ND + c0])       = __floats2half2_rn(v0, v1);
            *reinterpret_cast<__half2*>(&Cout[(r0 + 8) * ND + c0]) = __floats2half2_rn(v2, v3);
        }
    }
}

// ============================================================
// LN: out[b,m,:] = LayerNorm(x[b,m,:] + P[b,m/4,:] + S[b,:])
// Warp per row; P and S are fp16.
// ============================================================
__global__ void __launch_bounds__(256)
ln_kernel(const float* __restrict__ x,
          const float* __restrict__ gamma,
          const float* __restrict__ beta,
          float* __restrict__ out)
{
    const int warp = threadIdx.x >> 5;
    const int lane = threadIdx.x & 31;
    const int row  = blockIdx.x * 8 + warp;      // b*96 + m
    const int b    = row / NCELLS;
    const int m    = row - b * NCELLS;
    const int line = m >> 2;

    const float4* xr = reinterpret_cast<const float4*>(x) + (size_t)row * (ND/4);
    const uint2*  pr = reinterpret_cast<const uint2*>(g_P + ((size_t)b * NLINES + line) * ND);
    const uint2*  sr = reinterpret_cast<const uint2*>(g_S + (size_t)b * ND);

    float4 v[4];
    float s = 0.f, sq = 0.f;
    #pragma unroll
    for (int j = 0; j < 4; j++) {
        const int t = lane + j * 32;
        float4 xv = xr[t];
        uint2 pu = pr[t], su = sr[t];
        float2 p01 = __half22float2(*(__half2*)&pu.x);
        float2 p23 = __half22float2(*(__half2*)&pu.y);
        float2 s01 = __half22float2(*(__half2*)&su.x);
        float2 s23 = __half22float2(*(__half2*)&su.y);
        float4 w = make_float4(xv.x + p01.x + s01.x, xv.y + p01.y + s01.y,
                               xv.z + p23.x + s23.x, xv.w + p23.y + s23.y);
        v[j] = w;
        s  += w.x + w.y + w.z + w.w;
        sq += w.x*w.x + w.y*w.y + w.z*w.z + w.w*w.w;
    }
    #pragma unroll
    for (int o = 16; o; o >>= 1) {
        s  += __shfl_xor_sync(0xffffffffu, s,  o);
        sq += __shfl_xor_sync(0xffffffffu, sq, o);
    }
    const float mean = s * (1.0f / ND);
    const float var  = sq * (1.0f / ND) - mean * mean;
    const float inv  = rsqrtf(var + 1e-5f);

    float4* orow = reinterpret_cast<float4*>(out) + (size_t)row * (ND/4);
    #pragma unroll
    for (int j = 0; j < 4; j++) {
        const int t = lane + j * 32;
        float4 gv = reinterpret_cast<const float4*>(gamma)[t];
        float4 bv = reinterpret_cast<const float4*>(beta)[t];
        float4 o;
        o.x = (v[j].x - mean) * inv * gv.x + bv.x;
        o.y = (v[j].y - mean) * inv * gv.y + bv.y;
        o.z = (v[j].z - mean) * inv * gv.z + bv.z;
        o.w = (v[j].w - mean) * inv * gv.w + bv.w;
        orow[t] = o;
    }
}

// ============================================================
// launch
// ============================================================
extern "C" void kernel_launch(void* const* d_in, const int* in_sizes, int n_in,
                              void* d_out, int out_size)
{
    const float* x     = (const float*)d_in[0];
    const float* W1    = (const float*)d_in[2];
    const float* b1    = (const float*)d_in[3];
    const float* W2    = (const float*)d_in[4];
    const float* b2    = (const float*)d_in[5];
    const float* G1    = (const float*)d_in[6];
    const float* gb1   = (const float*)d_in[7];
    const float* G2    = (const float*)d_in[8];
    const float* gb2   = (const float*)d_in[9];
    const float* gamma = (const float*)d_in[10];
    const float* beta  = (const float*)d_in[11];
    float* out = (float*)d_out;

    __half *pLC, *pGC, *pH, *pP, *pHg, *pS, *pWt;
    cudaGetSymbolAddress((void**)&pLC, g_LC);
    cudaGetSymbolAddress((void**)&pGC, g_GC);
    cudaGetSymbolAddress((void**)&pH,  g_H);
    cudaGetSymbolAddress((void**)&pP,  g_P);
    cudaGetSymbolAddress((void**)&pHg, g_Hg);
    cudaGetSymbolAddress((void**)&pS,  g_S);
    cudaGetSymbolAddress((void**)&pWt, g_Wt);
    __half* pW1t = pWt + 0 * (size_t)ND * ND;
    __half* pW2t = pWt + 1 * (size_t)ND * ND;
    __half* pG1t = pWt + 2 * (size_t)ND * ND;
    __half* pG2t = pWt + 3 * (size_t)ND * ND;

    cudaFuncSetAttribute(gemm_kernel<true >, cudaFuncAttributeMaxDynamicSharedMemorySize, SMEM_B);
    cudaFuncSetAttribute(gemm_kernel<false>, cudaFuncAttributeMaxDynamicSharedMemorySize, SMEM_B);

    // 1) weights
    wconv_all_kernel<<<dim3(16, 16, 4), dim3(32, 8)>>>(W1, W2, G1, G2);

    // 2) gather reductions
    reduce_kernel<<<NB, 128>>>(x);

    // 3) stage 1 (mish): big + small fused
    const int mb_big = NROWS / 128, mb_sm = NB / 128;   // 384, 16
    gemm_kernel<true ><<<dim3(mb_big + mb_sm, 4), 256, SMEM_B>>>(
        pLC, pW1t, b1, pH, mb_big, pGC, pG1t, gb1, pHg);

    // 4) stage 2 (linear): big + small fused
    gemm_kernel<false><<<dim3(mb_big + mb_sm, 4), 256, SMEM_B>>>(
        pH, pW2t, b2, pP, mb_big, pHg, pG2t, gb2, pS);

    // 5) combine + LayerNorm
    ln_kernel<<<NB * NCELLS / 8, 256>>>(x, gamma, beta, out);
}

// round 9
// speedup vs baseline: 2.0716x; 1.0402x over previous
#include <cuda_runtime.h>
#include <cuda_fp16.h>
#include <cstdint>

#define NB     2048
#define NCELLS 96
#define NLINES 24
#define ND     512
#define NROWS  (NB * NLINES)   // 49152

// -------- scratch (device globals; allocation-free) --------
__device__ __align__(1024) __half g_LC[(size_t)NROWS * ND];
__device__ __align__(1024) __half g_GC[(size_t)NB * ND];
__device__ __align__(1024) __half g_H [(size_t)NROWS * ND];
__device__ __align__(1024) __half g_P [(size_t)NROWS * ND];
__device__ __align__(1024) __half g_Hg[(size_t)NB * ND];
__device__ __align__(1024) __half g_S [(size_t)NB * ND];
__device__ __align__(1024) __half g_Wt[4][(size_t)ND * ND];   // weights transposed [n][k] fp16

// ============================================================
// prep: blocks [0,1024): weight transpose fp32[k][n] -> fp16[n][k]
//       blocks [1024,3072): per-batch reduction -> fp16 LC / GC
// ============================================================
__global__ void __launch_bounds__(256)
prep_kernel(const float* __restrict__ x,
            const float* __restrict__ W1, const float* __restrict__ W2,
            const float* __restrict__ G1, const float* __restrict__ G2)
{
    __shared__ float tile[32][33];
    const int tid = threadIdx.x;

    if (blockIdx.x < 1024) {
        // ---- weight convert/transpose ----
        const int z   = blockIdx.x >> 8;          // which weight
        const int blk = blockIdx.x & 255;         // 16x16 tiles
        const float* W = (z == 0) ? W1 : (z == 1) ? W2 : (z == 2) ? G1 : G2;
        __half* Wt = &g_Wt[z][0];
        const int n0 = (blk & 15) * 32, k0 = (blk >> 4) * 32;
        const int tx = tid & 31, ty = tid >> 5;   // 32 x 8
        #pragma unroll
        for (int i = ty; i < 32; i += 8)
            tile[i][tx] = W[(size_t)(k0 + i) * ND + n0 + tx];
        __syncthreads();
        #pragma unroll
        for (int i = ty; i < 32; i += 8)
            Wt[(size_t)(n0 + i) * ND + k0 + tx] = __float2half(tile[tx][i]);
        return;
    }

    // ---- reduction: one batch per block, 128 active threads ----
    if (tid >= 128) return;
    const int b = blockIdx.x - 1024;
    const int t = tid;                               // 0..127, owns 4 d's
    const float4* xr = reinterpret_cast<const float4*>(x) + (size_t)b * NCELLS * (ND/4) + t;

    float tx_ = 0.f, ty_ = 0.f, tz_ = 0.f, tw_ = 0.f;
    #pragma unroll 4
    for (int g = 0; g < NLINES; g++) {
        float4 v0 = xr[(g*4 + 0) * (ND/4)];
        float4 v1 = xr[(g*4 + 1) * (ND/4)];
        float4 v2 = xr[(g*4 + 2) * (ND/4)];
        float4 v3 = xr[(g*4 + 3) * (ND/4)];
        float sx = v0.x + v1.x + v2.x + v3.x;
        float sy = v0.y + v1.y + v2.y + v3.y;
        float sz = v0.z + v1.z + v2.z + v3.z;
        float sw = v0.w + v1.w + v2.w + v3.w;
        __half2 lo = __floats2half2_rn(sx * 0.25f, sy * 0.25f);
        __half2 hi = __floats2half2_rn(sz * 0.25f, sw * 0.25f);
        uint2 pk = make_uint2(*(uint32_t*)&lo, *(uint32_t*)&hi);
        *reinterpret_cast<uint2*>(&g_LC[((size_t)b * NLINES + g) * ND + t * 4]) = pk;
        tx_ += sx; ty_ += sy; tz_ += sz; tw_ += sw;
    }
    const float inv96 = 1.0f / 96.0f;
    __half2 lo = __floats2half2_rn(tx_ * inv96, ty_ * inv96);
    __half2 hi = __floats2half2_rn(tz_ * inv96, tw_ * inv96);
    uint2 pk = make_uint2(*(uint32_t*)&lo, *(uint32_t*)&hi);
    *reinterpret_cast<uint2*>(&g_GC[(size_t)b * ND + t * 4]) = pk;
}

// ============================================================
// FP16 GEMM (ldmatrix + m16n8k16, pipelined frags)
// BM=128 BN=128 BK=64, 3-stage cp.async, 256 threads,
// 8 warps (4m x 2n), warp tile 32x64. Two problems per launch.
// ============================================================
__device__ __forceinline__ float mish_f(float v)
{
    float sp = log1pf(expf(v));
    return v * tanhf(sp);
}

#define BK      64
#define SPAD    72                        // 64 data + 8 pad halfs -> 144B row stride
#define TILE_H  (128 * SPAD)
#define STAGE_H (2 * TILE_H)
#define NSTAGE  3
#define SMEM_B  (NSTAGE * STAGE_H * 2)    // 110592 bytes

#define LDMX4(r0, r1, r2, r3, addr) \
    asm volatile("ldmatrix.sync.aligned.m8n8.x4.shared.b16 {%0,%1,%2,%3}, [%4];" \
                 : "=r"(r0), "=r"(r1), "=r"(r2), "=r"(r3) : "r"(addr))

#define MMA16816(acc, af, b0, b1) \
    asm volatile("mma.sync.aligned.m16n8k16.row.col.f32.f16.f16.f32 " \
                 "{%0,%1,%2,%3},{%4,%5,%6,%7},{%8,%9},{%0,%1,%2,%3};\n" \
                 : "+f"((acc)[0]), "+f"((acc)[1]), "+f"((acc)[2]), "+f"((acc)[3]) \
                 : "r"((af)[0]), "r"((af)[1]), "r"((af)[2]), "r"((af)[3]), \
                   "r"(b0), "r"(b1))

template<bool MISH>
__global__ void __launch_bounds__(256, 2)
gemm_kernel(const __half* __restrict__ A0, const __half* __restrict__ B0,
            const float* __restrict__ bias0, __half* __restrict__ C0, int mb0,
            const __half* __restrict__ A1, const __half* __restrict__ B1,
            const float* __restrict__ bias1, __half* __restrict__ C1)
{
    extern __shared__ __half smem[];

    const __half* A;  const __half* Bt;  const float* bias;  __half* Cout;
    size_t bm;
    if ((int)blockIdx.x < mb0) { A = A0; Bt = B0; bias = bias0; Cout = C0; bm = (size_t)blockIdx.x * 128; }
    else                       { A = A1; Bt = B1; bias = bias1; Cout = C1; bm = (size_t)(blockIdx.x - mb0) * 128; }
    const int bn = blockIdx.y * 128;

    const int tid  = threadIdx.x;
    const int lane = tid & 31;
    const int warp = tid >> 5;
    const int wm = (warp >> 1) * 32;
    const int wn = (warp & 1) * 64;

    const uint32_t sbase = (uint32_t)__cvta_generic_to_shared(smem);
    auto load_chunk = [&](int kc, int buf) {
        const uint32_t st = sbase + buf * (STAGE_H * 2);
        #pragma unroll
        for (int j = 0; j < 4; j++) {
            const int idx = tid + 256 * j;
            const int row = idx >> 3, seg = idx & 7;
            uint32_t dst = st + row * (SPAD * 2) + seg * 16;
            const __half* src = A + (bm + row) * (size_t)ND + kc * BK + seg * 8;
            asm volatile("cp.async.cg.shared.global [%0],[%1],16;\n" :: "r"(dst), "l"(src));
        }
        #pragma unroll
        for (int j = 0; j < 4; j++) {
            const int idx = tid + 256 * j;
            const int row = idx >> 3, seg = idx & 7;
            uint32_t dst = st + (TILE_H * 2) + row * (SPAD * 2) + seg * 16;
            const __half* src = Bt + (size_t)(bn + row) * ND + kc * BK + seg * 8;
            asm volatile("cp.async.cg.shared.global [%0],[%1],16;\n" :: "r"(dst), "l"(src));
        }
        asm volatile("cp.async.commit_group;\n" ::);
    };

    uint32_t aoff[2], boff[4];
    #pragma unroll
    for (int mt = 0; mt < 2; mt++)
        aoff[mt] = (wm + mt * 16 + (lane & 15)) * (SPAD * 2) + ((lane >> 4) * 8) * 2;
    #pragma unroll
    for (int p = 0; p < 4; p++)
        boff[p] = (TILE_H * 2) +
                  (wn + p * 16 + ((lane >> 4) << 3) + (lane & 7)) * (SPAD * 2) +
                  (((lane >> 3) & 1) * 8) * 2;

    float acc[2][8][4];
    #pragma unroll
    for (int mt = 0; mt < 2; mt++)
        #pragma unroll
        for (int nt = 0; nt < 8; nt++)
            #pragma unroll
            for (int k = 0; k < 4; k++) acc[mt][nt][k] = 0.f;

    load_chunk(0, 0);
    load_chunk(1, 1);

    for (int i = 0; i < 8; i++) {
        if (i < 7) asm volatile("cp.async.wait_group 1;\n" ::);
        else       asm volatile("cp.async.wait_group 0;\n" ::);
        __syncthreads();
        if (i + 2 < 8) load_chunk(i + 2, (i + 2) % 3);
        const uint32_t st = sbase + (i % 3) * (STAGE_H * 2);

        // double-buffered fragments over the 4 k-steps
        uint32_t a[2][2][4], b[2][4][4];
        #pragma unroll
        for (int mt = 0; mt < 2; mt++)
            LDMX4(a[0][mt][0], a[0][mt][1], a[0][mt][2], a[0][mt][3], st + aoff[mt]);
        #pragma unroll
        for (int p = 0; p < 4; p++)
            LDMX4(b[0][p][0], b[0][p][1], b[0][p][2], b[0][p][3], st + boff[p]);

        #pragma unroll
        for (int kk = 0; kk < 4; kk++) {
            const int cur = kk & 1, nxt = cur ^ 1;
            if (kk < 3) {
                const uint32_t kb = (kk + 1) * 32;    // bytes: 16 halfs
                #pragma unroll
                for (int mt = 0; mt < 2; mt++)
                    LDMX4(a[nxt][mt][0], a[nxt][mt][1], a[nxt][mt][2], a[nxt][mt][3],
                          st + aoff[mt] + kb);
                #pragma unroll
                for (int p = 0; p < 4; p++)
                    LDMX4(b[nxt][p][0], b[nxt][p][1], b[nxt][p][2], b[nxt][p][3],
                          st + boff[p] + kb);
            }
            #pragma unroll
            for (int mt = 0; mt < 2; mt++)
                #pragma unroll
                for (int p = 0; p < 4; p++) {
                    MMA16816(acc[mt][2*p],     a[cur][mt], b[cur][p][0], b[cur][p][1]);
                    MMA16816(acc[mt][2*p + 1], a[cur][mt], b[cur][p][2], b[cur][p][3]);
                }
        }
    }

    // ---- epilogue: bias (+mish), fp16 stores ----
    const int fr = lane >> 2;
    const int fc = (lane & 3) * 2;
    #pragma unroll
    for (int mt = 0; mt < 2; mt++) {
        #pragma unroll
        for (int nt = 0; nt < 8; nt++) {
            const size_t r0 = bm + wm + mt * 16 + fr;
            const int    c0 = bn + wn + nt * 8 + fc;
            const float bv0 = bias[c0], bv1 = bias[c0 + 1];
            float v0 = acc[mt][nt][0] + bv0;
            float v1 = acc[mt][nt][1] + bv1;
            float v2 = acc[mt][nt][2] + bv0;
            float v3 = acc[mt][nt][3] + bv1;
            if (MISH) { v0 = mish_f(v0); v1 = mish_f(v1); v2 = mish_f(v2); v3 = mish_f(v3); }
            *reinterpret_cast<__half2*>(&Cout[r0 * ND + c0])       = __floats2half2_rn(v0, v1);
            *reinterpret_cast<__half2*>(&Cout[(r0 + 8) * ND + c0]) = __floats2half2_rn(v2, v3);
        }
    }
}

// ============================================================
// LN: out[b,m,:] = LayerNorm(x[b,m,:] + P[b,m/4,:] + S[b,:])
// ============================================================
__global__ void __launch_bounds__(256)
ln_kernel(const float* __restrict__ x,
          const float* __restrict__ gamma,
          const float* __restrict__ beta,
          float* __restrict__ out)
{
    const int warp = threadIdx.x >> 5;
    const int lane = threadIdx.x & 31;
    const int row  = blockIdx.x * 8 + warp;      // b*96 + m
    const int b    = row / NCELLS;
    const int m    = row - b * NCELLS;
    const int line = m >> 2;

    const float4* xr = reinterpret_cast<const float4*>(x) + (size_t)row * (ND/4);
    const uint2*  pr = reinterpret_cast<const uint2*>(g_P + ((size_t)b * NLINES + line) * ND);
    const uint2*  sr = reinterpret_cast<const uint2*>(g_S + (size_t)b * ND);

    float4 v[4];
    float s = 0.f, sq = 0.f;
    #pragma unroll
    for (int j = 0; j < 4; j++) {
        const int t = lane + j * 32;
        float4 xv = xr[t];
        uint2 pu = pr[t], su = sr[t];
        float2 p01 = __half22float2(*(__half2*)&pu.x);
        float2 p23 = __half22float2(*(__half2*)&pu.y);
        float2 s01 = __half22float2(*(__half2*)&su.x);
        float2 s23 = __half22float2(*(__half2*)&su.y);
        float4 w = make_float4(xv.x + p01.x + s01.x, xv.y + p01.y + s01.y,
                               xv.z + p23.x + s23.x, xv.w + p23.y + s23.y);
        v[j] = w;
        s  += w.x + w.y + w.z + w.w;
        sq += w.x*w.x + w.y*w.y + w.z*w.z + w.w*w.w;
    }
    #pragma unroll
    for (int o = 16; o; o >>= 1) {
        s  += __shfl_xor_sync(0xffffffffu, s,  o);
        sq += __shfl_xor_sync(0xffffffffu, sq, o);
    }
    const float mean = s * (1.0f / ND);
    const float var  = sq * (1.0f / ND) - mean * mean;
    const float inv  = rsqrtf(var + 1e-5f);

    float4* orow = reinterpret_cast<float4*>(out) + (size_t)row * (ND/4);
    #pragma unroll
    for (int j = 0; j < 4; j++) {
        const int t = lane + j * 32;
        float4 gv = reinterpret_cast<const float4*>(gamma)[t];
        float4 bv = reinterpret_cast<const float4*>(beta)[t];
        float4 o;
        o.x = (v[j].x - mean) * inv * gv.x + bv.x;
        o.y = (v[j].y - mean) * inv * gv.y + bv.y;
        o.z = (v[j].z - mean) * inv * gv.z + bv.z;
        o.w = (v[j].w - mean) * inv * gv.w + bv.w;
        orow[t] = o;
    }
}

// ============================================================
// launch
// ============================================================
extern "C" void kernel_launch(void* const* d_in, const int* in_sizes, int n_in,
                              void* d_out, int out_size)
{
    const float* x     = (const float*)d_in[0];
    const float* W1    = (const float*)d_in[2];
    const float* b1    = (const float*)d_in[3];
    const float* W2    = (const float*)d_in[4];
    const float* b2    = (const float*)d_in[5];
    const float* G1    = (const float*)d_in[6];
    const float* gb1   = (const float*)d_in[7];
    const float* G2    = (const float*)d_in[8];
    const float* gb2   = (const float*)d_in[9];
    const float* gamma = (const float*)d_in[10];
    const float* beta  = (const float*)d_in[11];
    float* out = (float*)d_out;

    __half *pLC, *pGC, *pH, *pP, *pHg, *pS, *pWt;
    cudaGetSymbolAddress((void**)&pLC, g_LC);
    cudaGetSymbolAddress((void**)&pGC, g_GC);
    cudaGetSymbolAddress((void**)&pH,  g_H);
    cudaGetSymbolAddress((void**)&pP,  g_P);
    cudaGetSymbolAddress((void**)&pHg, g_Hg);
    cudaGetSymbolAddress((void**)&pS,  g_S);
    cudaGetSymbolAddress((void**)&pWt, g_Wt);
    __half* pW1t = pWt + 0 * (size_t)ND * ND;
    __half* pW2t = pWt + 1 * (size_t)ND * ND;
    __half* pG1t = pWt + 2 * (size_t)ND * ND;
    __half* pG2t = pWt + 3 * (size_t)ND * ND;

    cudaFuncSetAttribute(gemm_kernel<true >, cudaFuncAttributeMaxDynamicSharedMemorySize, SMEM_B);
    cudaFuncSetAttribute(gemm_kernel<false>, cudaFuncAttributeMaxDynamicSharedMemorySize, SMEM_B);

    // 1) weights + reductions, one launch
    prep_kernel<<<3072, 256>>>(x, W1, W2, G1, G2);

    // 2) stage 1 (mish): big + small fused
    const int mb_big = NROWS / 128, mb_sm = NB / 128;   // 384, 16
    gemm_kernel<true ><<<dim3(mb_big + mb_sm, 4), 256, SMEM_B>>>(
        pLC, pW1t, b1, pH, mb_big, pGC, pG1t, gb1, pHg);

    // 3) stage 2 (linear): big + small fused
    gemm_kernel<false><<<dim3(mb_big + mb_sm, 4), 256, SMEM_B>>>(
        pH, pW2t, b2, pP, mb_big, pHg, pG2t, gb2, pS);

    // 4) combine + LayerNorm
    ln_kernel<<<NB * NCELLS / 8, 256>>>(x, gamma, beta, out);
}

// round 10
// speedup vs baseline: 2.1790x; 1.0519x over previous
#include <cuda_runtime.h>
#include <cuda_fp16.h>
#include <cstdint>

#define NB     2048
#define NCELLS 96
#define NLINES 24
#define ND     512
#define NROWS  (NB * NLINES)   // 49152

// -------- scratch (device globals; allocation-free) --------
__device__ __align__(1024) __half g_LC[(size_t)NROWS * ND];
__device__ __align__(1024) __half g_GC[(size_t)NB * ND];
__device__ __align__(1024) __half g_H [(size_t)NROWS * ND];
__device__ __align__(1024) __half g_P [(size_t)NROWS * ND];
__device__ __align__(1024) __half g_Hg[(size_t)NB * ND];
__device__ __align__(1024) __half g_S [(size_t)NB * ND];
__device__ __align__(1024) __half g_Wt[4][(size_t)ND * ND];   // weights transposed [n][k] fp16

// ============================================================
// prep: blocks [0,1024): weight transpose fp32[k][n] -> fp16[n][k]
//       blocks [1024,2048): reduction, 2 batches per block
// ============================================================
__global__ void __launch_bounds__(256)
prep_kernel(const float* __restrict__ x,
            const float* __restrict__ W1, const float* __restrict__ W2,
            const float* __restrict__ G1, const float* __restrict__ G2)
{
    __shared__ float tile[32][33];
    const int tid = threadIdx.x;

    if (blockIdx.x < 1024) {
        // ---- weight convert/transpose ----
        const int z   = blockIdx.x >> 8;
        const int blk = blockIdx.x & 255;
        const float* W = (z == 0) ? W1 : (z == 1) ? W2 : (z == 2) ? G1 : G2;
        __half* Wt = &g_Wt[z][0];
        const int n0 = (blk & 15) * 32, k0 = (blk >> 4) * 32;
        const int tx = tid & 31, ty = tid >> 5;
        #pragma unroll
        for (int i = ty; i < 32; i += 8)
            tile[i][tx] = W[(size_t)(k0 + i) * ND + n0 + tx];
        __syncthreads();
        #pragma unroll
        for (int i = ty; i < 32; i += 8)
            Wt[(size_t)(n0 + i) * ND + k0 + tx] = __float2half(tile[tx][i]);
        return;
    }

    // ---- reduction: 2 batches per block (half-blocks of 128 threads) ----
    const int b = (blockIdx.x - 1024) * 2 + (tid >> 7);
    const int t = tid & 127;                         // 0..127, owns 4 d's
    const float4* xr = reinterpret_cast<const float4*>(x) + (size_t)b * NCELLS * (ND/4) + t;

    float tx_ = 0.f, ty_ = 0.f, tz_ = 0.f, tw_ = 0.f;
    #pragma unroll 4
    for (int g = 0; g < NLINES; g++) {
        float4 v0 = __ldcs(&xr[(g*4 + 0) * (ND/4)]);
        float4 v1 = __ldcs(&xr[(g*4 + 1) * (ND/4)]);
        float4 v2 = __ldcs(&xr[(g*4 + 2) * (ND/4)]);
        float4 v3 = __ldcs(&xr[(g*4 + 3) * (ND/4)]);
        float sx = v0.x + v1.x + v2.x + v3.x;
        float sy = v0.y + v1.y + v2.y + v3.y;
        float sz = v0.z + v1.z + v2.z + v3.z;
        float sw = v0.w + v1.w + v2.w + v3.w;
        __half2 lo = __floats2half2_rn(sx * 0.25f, sy * 0.25f);
        __half2 hi = __floats2half2_rn(sz * 0.25f, sw * 0.25f);
        uint2 pk = make_uint2(*(uint32_t*)&lo, *(uint32_t*)&hi);
        *reinterpret_cast<uint2*>(&g_LC[((size_t)b * NLINES + g) * ND + t * 4]) = pk;
        tx_ += sx; ty_ += sy; tz_ += sz; tw_ += sw;
    }
    const float inv96 = 1.0f / 96.0f;
    __half2 lo = __floats2half2_rn(tx_ * inv96, ty_ * inv96);
    __half2 hi = __floats2half2_rn(tz_ * inv96, tw_ * inv96);
    uint2 pk = make_uint2(*(uint32_t*)&lo, *(uint32_t*)&hi);
    *reinterpret_cast<uint2*>(&g_GC[(size_t)b * ND + t * 4]) = pk;
}

// ============================================================
// FP16 GEMM (ldmatrix + m16n8k16, pipelined frags)
// BM=128 BN=128 BK=64, 3-stage cp.async, 256 threads.
// ============================================================
// fast mish: t=e^v, mish = v*(t^2+2t)/(t^2+2t+2); exact limits both sides
__device__ __forceinline__ float mish_f(float v)
{
    float t   = __expf(v);
    float num = t * (t + 2.0f);
    float r   = v * __fdividef(num, num + 2.0f);
    return (v > 30.0f) ? v : r;
}

#define BK      64
#define SPAD    72
#define TILE_H  (128 * SPAD)
#define STAGE_H (2 * TILE_H)
#define NSTAGE  3
#define SMEM_B  (NSTAGE * STAGE_H * 2)    // 110592 bytes

#define LDMX4(r0, r1, r2, r3, addr) \
    asm volatile("ldmatrix.sync.aligned.m8n8.x4.shared.b16 {%0,%1,%2,%3}, [%4];" \
                 : "=r"(r0), "=r"(r1), "=r"(r2), "=r"(r3) : "r"(addr))

#define MMA16816(acc, af, b0, b1) \
    asm volatile("mma.sync.aligned.m16n8k16.row.col.f32.f16.f16.f32 " \
                 "{%0,%1,%2,%3},{%4,%5,%6,%7},{%8,%9},{%0,%1,%2,%3};\n" \
                 : "+f"((acc)[0]), "+f"((acc)[1]), "+f"((acc)[2]), "+f"((acc)[3]) \
                 : "r"((af)[0]), "r"((af)[1]), "r"((af)[2]), "r"((af)[3]), \
                   "r"(b0), "r"(b1))

template<bool MISH>
__global__ void __launch_bounds__(256, 2)
gemm_kernel(const __half* __restrict__ A0, const __half* __restrict__ B0,
            const float* __restrict__ bias0, __half* __restrict__ C0, int mb0,
            const __half* __restrict__ A1, const __half* __restrict__ B1,
            const float* __restrict__ bias1, __half* __restrict__ C1)
{
    extern __shared__ __half smem[];

    const __half* A;  const __half* Bt;  const float* bias;  __half* Cout;
    size_t bm;
    if ((int)blockIdx.x < mb0) { A = A0; Bt = B0; bias = bias0; Cout = C0; bm = (size_t)blockIdx.x * 128; }
    else                       { A = A1; Bt = B1; bias = bias1; Cout = C1; bm = (size_t)(blockIdx.x - mb0) * 128; }
    const int bn = blockIdx.y * 128;

    const int tid  = threadIdx.x;
    const int lane = tid & 31;
    const int warp = tid >> 5;
    const int wm = (warp >> 1) * 32;
    const int wn = (warp & 1) * 64;

    const uint32_t sbase = (uint32_t)__cvta_generic_to_shared(smem);
    auto load_chunk = [&](int kc, int buf) {
        const uint32_t st = sbase + buf * (STAGE_H * 2);
        #pragma unroll
        for (int j = 0; j < 4; j++) {
            const int idx = tid + 256 * j;
            const int row = idx >> 3, seg = idx & 7;
            uint32_t dst = st + row * (SPAD * 2) + seg * 16;
            const __half* src = A + (bm + row) * (size_t)ND + kc * BK + seg * 8;
            asm volatile("cp.async.cg.shared.global [%0],[%1],16;\n" :: "r"(dst), "l"(src));
        }
        #pragma unroll
        for (int j = 0; j < 4; j++) {
            const int idx = tid + 256 * j;
            const int row = idx >> 3, seg = idx & 7;
            uint32_t dst = st + (TILE_H * 2) + row * (SPAD * 2) + seg * 16;
            const __half* src = Bt + (size_t)(bn + row) * ND + kc * BK + seg * 8;
            asm volatile("cp.async.cg.shared.global [%0],[%1],16;\n" :: "r"(dst), "l"(src));
        }
        asm volatile("cp.async.commit_group;\n" ::);
    };

    uint32_t aoff[2], boff[4];
    #pragma unroll
    for (int mt = 0; mt < 2; mt++)
        aoff[mt] = (wm + mt * 16 + (lane & 15)) * (SPAD * 2) + ((lane >> 4) * 8) * 2;
    #pragma unroll
    for (int p = 0; p < 4; p++)
        boff[p] = (TILE_H * 2) +
                  (wn + p * 16 + ((lane >> 4) << 3) + (lane & 7)) * (SPAD * 2) +
                  (((lane >> 3) & 1) * 8) * 2;

    float acc[2][8][4];
    #pragma unroll
    for (int mt = 0; mt < 2; mt++)
        #pragma unroll
        for (int nt = 0; nt < 8; nt++)
            #pragma unroll
            for (int k = 0; k < 4; k++) acc[mt][nt][k] = 0.f;

    load_chunk(0, 0);
    load_chunk(1, 1);

    for (int i = 0; i < 8; i++) {
        if (i < 7) asm volatile("cp.async.wait_group 1;\n" ::);
        else       asm volatile("cp.async.wait_group 0;\n" ::);
        __syncthreads();
        if (i + 2 < 8) load_chunk(i + 2, (i + 2) % 3);
        const uint32_t st = sbase + (i % 3) * (STAGE_H * 2);

        uint32_t a[2][2][4], b[2][4][4];
        #pragma unroll
        for (int mt = 0; mt < 2; mt++)
            LDMX4(a[0][mt][0], a[0][mt][1], a[0][mt][2], a[0][mt][3], st + aoff[mt]);
        #pragma unroll
        for (int p = 0; p < 4; p++)
            LDMX4(b[0][p][0], b[0][p][1], b[0][p][2], b[0][p][3], st + boff[p]);

        #pragma unroll
        for (int kk = 0; kk < 4; kk++) {
            const int cur = kk & 1, nxt = cur ^ 1;
            if (kk < 3) {
                const uint32_t kb = (kk + 1) * 32;
                #pragma unroll
                for (int mt = 0; mt < 2; mt++)
                    LDMX4(a[nxt][mt][0], a[nxt][mt][1], a[nxt][mt][2], a[nxt][mt][3],
                          st + aoff[mt] + kb);
                #pragma unroll
                for (int p = 0; p < 4; p++)
                    LDMX4(b[nxt][p][0], b[nxt][p][1], b[nxt][p][2], b[nxt][p][3],
                          st + boff[p] + kb);
            }
            #pragma unroll
            for (int mt = 0; mt < 2; mt++)
                #pragma unroll
                for (int p = 0; p < 4; p++) {
                    MMA16816(acc[mt][2*p],     a[cur][mt], b[cur][p][0], b[cur][p][1]);
                    MMA16816(acc[mt][2*p + 1], a[cur][mt], b[cur][p][2], b[cur][p][3]);
                }
        }
    }

    // ---- epilogue: bias (+fast mish), fp16 stores ----
    const int fr = lane >> 2;
    const int fc = (lane & 3) * 2;
    #pragma unroll
    for (int mt = 0; mt < 2; mt++) {
        #pragma unroll
        for (int nt = 0; nt < 8; nt++) {
            const size_t r0 = bm + wm + mt * 16 + fr;
            const int    c0 = bn + wn + nt * 8 + fc;
            const float bv0 = bias[c0], bv1 = bias[c0 + 1];
            float v0 = acc[mt][nt][0] + bv0;
            float v1 = acc[mt][nt][1] + bv1;
            float v2 = acc[mt][nt][2] + bv0;
            float v3 = acc[mt][nt][3] + bv1;
            if (MISH) { v0 = mish_f(v0); v1 = mish_f(v1); v2 = mish_f(v2); v3 = mish_f(v3); }
            *reinterpret_cast<__half2*>(&Cout[r0 * ND + c0])       = __floats2half2_rn(v0, v1);
            *reinterpret_cast<__half2*>(&Cout[(r0 + 8) * ND + c0]) = __floats2half2_rn(v2, v3);
        }
    }
}

// ============================================================
// LN: out[b,m,:] = LayerNorm(x[b,m,:] + P[b,m/4,:] + S[b,:])
// Warp per row; x streamed (.cs), out streamed (.cs).
// ============================================================
__global__ void __launch_bounds__(256)
ln_kernel(const float* __restrict__ x,
          const float* __restrict__ gamma,
          const float* __restrict__ beta,
          float* __restrict__ out)
{
    const int warp = threadIdx.x >> 5;
    const int lane = threadIdx.x & 31;
    const int row  = blockIdx.x * 8 + warp;      // b*96 + m
    const int b    = row / NCELLS;
    const int m    = row - b * NCELLS;
    const int line = m >> 2;

    const float4* xr = reinterpret_cast<const float4*>(x) + (size_t)row * (ND/4);
    const uint2*  pr = reinterpret_cast<const uint2*>(g_P + ((size_t)b * NLINES + line) * ND);
    const uint2*  sr = reinterpret_cast<const uint2*>(g_S + (size_t)b * ND);

    float4 v[4];
    float s = 0.f, sq = 0.f;
    #pragma unroll
    for (int j = 0; j < 4; j++) {
        const int t = lane + j * 32;
        float4 xv = __ldcs(&xr[t]);
        uint2 pu = pr[t], su = sr[t];
        float2 p01 = __half22float2(*(__half2*)&pu.x);
        float2 p23 = __half22float2(*(__half2*)&pu.y);
        float2 s01 = __half22float2(*(__half2*)&su.x);
        float2 s23 = __half22float2(*(__half2*)&su.y);
        float4 w = make_float4(xv.x + p01.x + s01.x, xv.y + p01.y + s01.y,
                               xv.z + p23.x + s23.x, xv.w + p23.y + s23.y);
        v[j] = w;
        s  += w.x + w.y + w.z + w.w;
        sq += w.x*w.x + w.y*w.y + w.z*w.z + w.w*w.w;
    }
    #pragma unroll
    for (int o = 16; o; o >>= 1) {
        s  += __shfl_xor_sync(0xffffffffu, s,  o);
        sq += __shfl_xor_sync(0xffffffffu, sq, o);
    }
    const float mean = s * (1.0f / ND);
    const float var  = sq * (1.0f / ND) - mean * mean;
    const float inv  = rsqrtf(var + 1e-5f);

    float4* orow = reinterpret_cast<float4*>(out) + (size_t)row * (ND/4);
    #pragma unroll
    for (int j = 0; j < 4; j++) {
        const int t = lane + j * 32;
        float4 gv = reinterpret_cast<const float4*>(gamma)[t];
        float4 bv = reinterpret_cast<const float4*>(beta)[t];
        float4 o;
        o.x = (v[j].x - mean) * inv * gv.x + bv.x;
        o.y = (v[j].y - mean) * inv * gv.y + bv.y;
        o.z = (v[j].z - mean) * inv * gv.z + bv.z;
        o.w = (v[j].w - mean) * inv * gv.w + bv.w;
        __stcs(&orow[t], o);
    }
}

// ============================================================
// launch
// ============================================================
extern "C" void kernel_launch(void* const* d_in, const int* in_sizes, int n_in,
                              void* d_out, int out_size)
{
    const float* x     = (const float*)d_in[0];
    const float* W1    = (const float*)d_in[2];
    const float* b1    = (const float*)d_in[3];
    const float* W2    = (const float*)d_in[4];
    const float* b2    = (const float*)d_in[5];
    const float* G1    = (const float*)d_in[6];
    const float* gb1   = (const float*)d_in[7];
    const float* G2    = (const float*)d_in[8];
    const float* gb2   = (const float*)d_in[9];
    const float* gamma = (const float*)d_in[10];
    const float* beta  = (const float*)d_in[11];
    float* out = (float*)d_out;

    __half *pLC, *pGC, *pH, *pP, *pHg, *pS, *pWt;
    cudaGetSymbolAddress((void**)&pLC, g_LC);
    cudaGetSymbolAddress((void**)&pGC, g_GC);
    cudaGetSymbolAddress((void**)&pH,  g_H);
    cudaGetSymbolAddress((void**)&pP,  g_P);
    cudaGetSymbolAddress((void**)&pHg, g_Hg);
    cudaGetSymbolAddress((void**)&pS,  g_S);
    cudaGetSymbolAddress((void**)&pWt, g_Wt);
    __half* pW1t = pWt + 0 * (size_t)ND * ND;
    __half* pW2t = pWt + 1 * (size_t)ND * ND;
    __half* pG1t = pWt + 2 * (size_t)ND * ND;
    __half* pG2t = pWt + 3 * (size_t)ND * ND;

    cudaFuncSetAttribute(gemm_kernel<true >, cudaFuncAttributeMaxDynamicSharedMemorySize, SMEM_B);
    cudaFuncSetAttribute(gemm_kernel<false>, cudaFuncAttributeMaxDynamicSharedMemorySize, SMEM_B);

    // 1) weights + reductions, one launch
    prep_kernel<<<2048, 256>>>(x, W1, W2, G1, G2);

    // 2) stage 1 (mish): big + small fused
    const int mb_big = NROWS / 128, mb_sm = NB / 128;   // 384, 16
    gemm_kernel<true ><<<dim3(mb_big + mb_sm, 4), 256, SMEM_B>>>(
        pLC, pW1t, b1, pH, mb_big, pGC, pG1t, gb1, pHg);

    // 3) stage 2 (linear): big + small fused
    gemm_kernel<false><<<dim3(mb_big + mb_sm, 4), 256, SMEM_B>>>(
        pH, pW2t, b2, pP, mb_big, pHg, pG2t, gb2, pS);

    // 4) combine + LayerNorm
    ln_kernel<<<NB * NCELLS / 8, 256>>>(x, gamma, beta, out);
}